// round 16
// baseline (speedup 1.0000x reference)
#include <cuda_runtime.h>
#include <cuda_bf16.h>
#include <math.h>
#include <stdint.h>

#define BATCH 4
#define TSEQ  4096
#define DMODEL 1024
#define HDIM  64
#define NROWS (BATCH*TSEQ)
#define NTILE (NROWS/128)

#define SCALE_Q 0.18033688011112042f   // log2(e)/8

// Scratch: preformatted bf16 hi/lo tiles (swizzled smem images)
__device__ __align__(16) __nv_bfloat16 g_qhi[NROWS*HDIM];
__device__ __align__(16) __nv_bfloat16 g_qlo[NROWS*HDIM];
__device__ __align__(16) __nv_bfloat16 g_khi[NROWS*HDIM];
__device__ __align__(16) __nv_bfloat16 g_klo[NROWS*HDIM];
__device__ __align__(16) __nv_bfloat16 g_vthi[NROWS*HDIM];
__device__ __align__(16) __nv_bfloat16 g_vtlo[NROWS*HDIM];
__device__ __align__(16) char g_wimg[16*3*16384];   // [chunk][m][hi 8KB | lo 8KB]
__device__ float g_ent;

__device__ __forceinline__ float ex2f_(float x){ float y; asm("ex2.approx.ftz.f32 %0, %1;" : "=f"(y) : "f"(x)); return y; }
__device__ __forceinline__ float lg2f_(float x){ float y; asm("lg2.approx.f32 %0, %1;" : "=f"(y) : "f"(x)); return y; }

__device__ __forceinline__ uint32_t pk2(float a, float b){
    uint32_t r;
    asm("cvt.rn.bf16x2.f32 %0, %1, %2;" : "=r"(r) : "f"(b), "f"(a));
    return r;
}
__device__ __forceinline__ uint32_t pk2lo(float a, float b, uint32_t u){
    float hi_a = __uint_as_float(u << 16);
    float hi_b = __uint_as_float(u & 0xffff0000u);
    return pk2(a - hi_a, b - hi_b);
}
__device__ __forceinline__ uint32_t smem_u32(const void* p){
    uint32_t a;
    asm("{ .reg .u64 t; cvta.to.shared.u64 t, %1; cvt.u32.u64 %0, t; }" : "=r"(a) : "l"(p));
    return a;
}
__device__ __forceinline__ void cpa16(uint32_t s, const void* g){
    asm volatile("cp.async.cg.shared.global [%0], [%1], 16;" :: "r"(s), "l"(g));
}
#define CPA_COMMIT() asm volatile("cp.async.commit_group;" ::: "memory")
#define CPA_WAIT0()  asm volatile("cp.async.wait_group 0;" ::: "memory")
#define CPA_WAIT1()  asm volatile("cp.async.wait_group 1;" ::: "memory")

// streaming store (evict-first): attn/out are write-once, never re-read
__device__ __forceinline__ void stg_cs2(float* p, float a, float b){
    asm volatile("st.global.cs.v2.f32 [%0], {%1, %2};" :: "l"(p), "f"(a), "f"(b) : "memory");
}

__device__ __forceinline__ void mma16816(float* c, const uint32_t* a, uint32_t b0, uint32_t b1){
    asm volatile("mma.sync.aligned.m16n8k16.row.col.f32.bf16.bf16.f32 "
        "{%0,%1,%2,%3}, {%4,%5,%6,%7}, {%8,%9}, {%0,%1,%2,%3};"
        : "+f"(c[0]), "+f"(c[1]), "+f"(c[2]), "+f"(c[3])
        : "r"(a[0]), "r"(a[1]), "r"(a[2]), "r"(a[3]), "r"(b0), "r"(b1));
}
__device__ __forceinline__ void ldsm4(uint32_t* r, uint32_t addr){
    asm volatile("ldmatrix.sync.aligned.m8n8.x4.shared.b16 {%0,%1,%2,%3}, [%4];"
        : "=r"(r[0]), "=r"(r[1]), "=r"(r[2]), "=r"(r[3]) : "r"(addr));
}

// Q/K/W tiles: 128B rows, row r, byte col cb (0..127)
__device__ __forceinline__ uint32_t swz(int r, int cb){
    return (uint32_t)(r*128 + (cb ^ ((r & 7) << 4)));
}
// VT tiles: 256B rows (128 keys bf16), swizzle within each 128B half
__device__ __forceinline__ uint32_t vswz(int h, int kb){
    return (uint32_t)(h*256 + (kb & 128) + ((kb & 127) ^ ((h & 7) << 4)));
}

// ---------------------------------------------------------------------------
// K0: W preformat. grid 48 (= chunk*3 + m), 256 threads. One 16KB image each.
// ---------------------------------------------------------------------------
__global__ __launch_bounds__(256) void wprep_kernel(
    const float* __restrict__ Wq,
    const float* __restrict__ Wk,
    const float* __restrict__ Wv)
{
    const int m = blockIdx.x % 3;
    const int c = blockIdx.x / 3;
    const float* W = (m == 0) ? Wq : ((m == 1) ? Wk : Wv);
    char* dst = g_wimg + (size_t)blockIdx.x * 16384;
    const int tid = threadIdx.x;
    if (blockIdx.x == 0 && tid == 0) g_ent = 0.0f;
    #pragma unroll
    for (int i = 0; i < 8; i++) {
        int p = i*256 + tid;
        int h = p >> 5, c2 = p & 31;
        float2 v = *(const float2*)&W[(size_t)h*DMODEL + c*64 + 2*c2];
        uint32_t u = pk2(v.x, v.y);
        uint32_t off = swz(h, c2*4);
        *(uint32_t*)(dst + off)        = u;
        *(uint32_t*)(dst + 8192 + off) = pk2lo(v.x, v.y, u);
    }
}

// ---------------------------------------------------------------------------
// K1: fused QKV projection (R13 — passing, near floor).
// ---------------------------------------------------------------------------
#define PJ_XSTG 0              // 2 x 32KB fp32 x staging
#define PJ_XIMG 65536          // xhi 16KB + xlo 16KB
#define PJ_WIMG 98304          // 2 x 48KB preformatted W images
#define SMEM_PROJ 196608
#define PSTG_STRIDE 66

__global__ __launch_bounds__(512, 1) void proj_kernel(const float* __restrict__ x)
{
    extern __shared__ char sm[];
    const int tile = blockIdx.x;
    const int row0 = tile * 128;
    const int tid  = threadIdx.x;
    const int w    = tid >> 5;
    const int lane = tid & 31;
    const int g    = lane >> 2;
    const int tq   = lane & 3;
    const int wm   = w & 7;
    const int wn   = w >> 3;
    const int wr   = 16 * wm;
    const uint32_t smb = smem_u32(sm);

    const int      rip = ((lane >> 4) & 1)*8 + (lane & 7);
    const uint32_t khb = ((lane >> 3) & 1)*16;
    const uint32_t swl = (uint32_t)((lane & 7) << 4);
    const int      ripA = ((lane >> 3) & 1)*8 + (lane & 7);
    const uint32_t khA  = (uint32_t)((lane >> 4) << 4);

    float acc[3][4][4];
    #pragma unroll
    for (int m = 0; m < 3; m++)
        #pragma unroll
        for (int n = 0; n < 4; n++)
            #pragma unroll
            for (int j = 0; j < 4; j++) acc[m][n][j] = 0.0f;

    {
        const char* xg = (const char*)(x + (size_t)row0*DMODEL);
        #pragma unroll
        for (int i = 0; i < 4; i++) {
            int p = i*512 + tid;
            int r = p >> 4, cb = (p & 15)*16;
            cpa16(smb + PJ_XSTG + (uint32_t)(r*256 + cb), xg + (size_t)r*4096 + cb);
        }
        const char* wg = g_wimg;
        #pragma unroll
        for (int i = 0; i < 6; i++) {
            uint32_t off = (uint32_t)(i*8192 + tid*16);
            cpa16(smb + PJ_WIMG + off, wg + off);
        }
        CPA_COMMIT();
    }

    for (int c = 0; c < 16; c++) {
        __syncthreads();
        if (c < 15) {
            const char* xg = (const char*)(x + (size_t)row0*DMODEL + (c+1)*64);
            const uint32_t xdst = smb + PJ_XSTG + (uint32_t)(((c+1)&1)*32768);
            #pragma unroll
            for (int i = 0; i < 4; i++) {
                int p = i*512 + tid;
                int r = p >> 4, cb = (p & 15)*16;
                cpa16(xdst + (uint32_t)(r*256 + cb), xg + (size_t)r*4096 + cb);
            }
            const char* wg = g_wimg + (size_t)(c+1)*49152;
            const uint32_t wdst = smb + PJ_WIMG + (uint32_t)(((c+1)&1)*49152);
            #pragma unroll
            for (int i = 0; i < 6; i++) {
                uint32_t off = (uint32_t)(i*8192 + tid*16);
                cpa16(wdst + off, wg + off);
            }
            CPA_COMMIT();
            CPA_WAIT1();
        } else {
            CPA_WAIT0();
        }
        __syncthreads();

        {
            const float* stg = (const float*)(sm + PJ_XSTG + (c&1)*32768);
            #pragma unroll
            for (int i = 0; i < 8; i++) {
                int p = i*512 + tid;
                int r = p >> 5, c2 = p & 31;
                float2 v = *(const float2*)&stg[r*64 + 2*c2];
                uint32_t u = pk2(v.x, v.y);
                uint32_t off = swz(r, c2*4);
                *(uint32_t*)(sm + PJ_XIMG + off)         = u;
                *(uint32_t*)(sm + PJ_XIMG + 16384 + off) = pk2lo(v.x, v.y, u);
            }
        }
        __syncthreads();

        const uint32_t xrowA = smb + PJ_XIMG + (uint32_t)((wr + ripA)*128);
        const uint32_t wbuf  = smb + PJ_WIMG + (uint32_t)((c&1)*49152);
        #pragma unroll
        for (int ks = 0; ks < 4; ks++) {
            uint32_t coA = ((uint32_t)(ks*32) | khA) ^ swl;
            uint32_t ah[4], al[4];
            ldsm4(ah, xrowA + coA);
            ldsm4(al, xrowA + 16384 + coA);
            uint32_t co = ((uint32_t)(ks*32) | khb) ^ swl;
            #pragma unroll
            for (int m = 0; m < 3; m++) {
                #pragma unroll
                for (int ntp = 0; ntp < 2; ntp++) {
                    uint32_t rowb = wbuf + (uint32_t)(m*16384 + (wn*32 + ntp*16 + rip)*128);
                    uint32_t bh[4], bl[4];
                    ldsm4(bh, rowb + co);
                    ldsm4(bl, rowb + 8192 + co);
                    mma16816(acc[m][2*ntp],   ah, bh[0], bh[1]);
                    mma16816(acc[m][2*ntp+1], ah, bh[2], bh[3]);
                    mma16816(acc[m][2*ntp],   ah, bl[0], bl[1]);
                    mma16816(acc[m][2*ntp+1], ah, bl[2], bl[3]);
                    mma16816(acc[m][2*ntp],   al, bh[0], bh[1]);
                    mma16816(acc[m][2*ntp+1], al, bh[2], bh[3]);
                }
            }
        }
    }

    #pragma unroll
    for (int m = 0; m < 2; m++) {
        const float sc = (m == 0) ? SCALE_Q : 1.0f;
        char* dhi = (char*)((m == 0) ? g_qhi : g_khi) + (size_t)tile*16384;
        char* dlo = (char*)((m == 0) ? g_qlo : g_klo) + (size_t)tile*16384;
        #pragma unroll
        for (int nt = 0; nt < 4; nt++) {
            float c0 = acc[m][nt][0]*sc, c1 = acc[m][nt][1]*sc;
            float c2 = acc[m][nt][2]*sc, c3 = acc[m][nt][3]*sc;
            int cb = wn*64 + nt*16 + tq*4;
            uint32_t u0 = pk2(c0, c1), u1 = pk2(c2, c3);
            *(uint32_t*)(dhi + swz(wr+g,   cb)) = u0;
            *(uint32_t*)(dhi + swz(wr+g+8, cb)) = u1;
            *(uint32_t*)(dlo + swz(wr+g,   cb)) = pk2lo(c0, c1, u0);
            *(uint32_t*)(dlo + swz(wr+g+8, cb)) = pk2lo(c2, c3, u1);
        }
    }

    __syncthreads();
    float* stg = (float*)sm;
    #pragma unroll
    for (int nt = 0; nt < 4; nt++) {
        int hc = wn*32 + nt*8 + tq*2;
        *(float2*)&stg[(wr+g)*PSTG_STRIDE + hc]   = make_float2(acc[2][nt][0], acc[2][nt][1]);
        *(float2*)&stg[(wr+g+8)*PSTG_STRIDE + hc] = make_float2(acc[2][nt][2], acc[2][nt][3]);
    }
    __syncthreads();
    {
        char* dhi = (char*)g_vthi + (size_t)tile*16384;
        char* dlo = (char*)g_vtlo + (size_t)tile*16384;
        int h = tid & 63, kp0 = tid >> 6;
        #pragma unroll
        for (int i = 0; i < 8; i++) {
            int pi = kp0 + 8*i;
            int k = 2*pi;
            float v0 = stg[k*PSTG_STRIDE + h];
            float v1 = stg[(k+1)*PSTG_STRIDE + h];
            uint32_t off = vswz(h, 4*pi);
            uint32_t u = pk2(v0, v1);
            *(uint32_t*)(dhi + off) = u;
            *(uint32_t*)(dlo + off) = pk2lo(v0, v1, u);
        }
    }
}

// ---------------------------------------------------------------------------
// K2: fused attention, two-pass, 256 threads. Pass B software-pipelined:
// per chunk: S-MMA(c) -> PV-MMA(c-1) (register P-frags) -> epilogue(c).
// K double-buffered (2x32KB), V triple-buffered (3x32KB), Q 32KB = 192KB.
// ---------------------------------------------------------------------------
#define OQHI 0
#define OQLO 16384
#define OKB  32768            // 2 x 32KB: [khi 16K | klo 16K]
#define OVB  98304            // 3 x 32KB: [vthi 16K | vtlo 16K]
#define SMEM_ATTN 196608

__global__ __launch_bounds__(256, 1) void attn2_kernel(float* __restrict__ attn,
                                                       float* __restrict__ out)
{
    extern __shared__ char sm[];
    __shared__ float s_ent[8];

    const int tid  = threadIdx.x;
    const int w    = tid >> 5;
    const int lane = tid & 31;
    const int g    = lane >> 2;
    const int tq   = lane & 3;
    const int b    = blockIdx.y;
    const int q0   = blockIdx.x * 128;
    const size_t rowg = (size_t)b*TSEQ + q0;
    const int wr  = 16 * w;
    const uint32_t smb = smem_u32(sm);

    const int      rip = ((lane >> 4) & 1)*8 + (lane & 7);
    const uint32_t khb = ((lane >> 3) & 1)*16;
    const uint32_t swl = (uint32_t)((lane & 7) << 4);

    const int tile_q  = b*(TSEQ/128) + blockIdx.x;
    const int tile_k0 = b*(TSEQ/128);

    {
        const char* gq_hi = (const char*)g_qhi + (size_t)tile_q*16384;
        const char* gq_lo = (const char*)g_qlo + (size_t)tile_q*16384;
        #pragma unroll
        for (int i = 0; i < 4; i++) {
            uint32_t off = (uint32_t)(i*4096 + tid*16);
            cpa16(smb + OQHI + off, gq_hi + off);
            cpa16(smb + OQLO + off, gq_lo + off);
        }
        const char* gk_hi = (const char*)g_khi + (size_t)tile_k0*16384;
        #pragma unroll
        for (int i = 0; i < 4; i++) {
            uint32_t off = (uint32_t)(i*4096 + tid*16);
            cpa16(smb + OKB + off, gk_hi + off);
        }
        CPA_COMMIT();
        CPA_WAIT0();
    }
    __syncthreads();

    uint32_t qh[4][4], ql[4][4];
    #pragma unroll
    for (int ks = 0; ks < 4; ks++) {
        int kb = ks*32 + tq*4;
        qh[ks][0] = *(const uint32_t*)(sm + OQHI + swz(wr+g,   kb));
        qh[ks][1] = *(const uint32_t*)(sm + OQHI + swz(wr+g+8, kb));
        qh[ks][2] = *(const uint32_t*)(sm + OQHI + swz(wr+g,   kb+16));
        qh[ks][3] = *(const uint32_t*)(sm + OQHI + swz(wr+g+8, kb+16));
        ql[ks][0] = *(const uint32_t*)(sm + OQLO + swz(wr+g,   kb));
        ql[ks][1] = *(const uint32_t*)(sm + OQLO + swz(wr+g+8, kb));
        ql[ks][2] = *(const uint32_t*)(sm + OQLO + swz(wr+g,   kb+16));
        ql[ks][3] = *(const uint32_t*)(sm + OQLO + swz(wr+g+8, kb+16));
    }

    // ====================== PASS A: rowsums Z (1-term) ======================
    // uses OKB slot-0 region as 2 x 16KB khi double buffer
    float Zr0 = 0.f, Zr1 = 0.f;
    for (int c = 0; c < TSEQ/128; c++) {
        __syncthreads();
        if (c < TSEQ/128 - 1) {
            const char* gk_hi = (const char*)g_khi + (size_t)(tile_k0 + c + 1)*16384;
            const uint32_t dst = smb + OKB + (uint32_t)(((c+1)&1)*16384);
            #pragma unroll
            for (int i = 0; i < 4; i++) {
                uint32_t off = (uint32_t)(i*4096 + tid*16);
                cpa16(dst + off, gk_hi + off);
            }
            CPA_COMMIT();
            CPA_WAIT1();
        } else {
            CPA_WAIT0();
        }
        __syncthreads();

        const uint32_t kb32 = smb + OKB + (uint32_t)((c&1)*16384);
        float sacc[16][4];
        #pragma unroll
        for (int n = 0; n < 16; n++)
            #pragma unroll
            for (int j = 0; j < 4; j++) sacc[n][j] = 0.0f;
        #pragma unroll
        for (int ntp = 0; ntp < 8; ntp++) {
            const uint32_t rowb = kb32 + (uint32_t)((ntp*16 + rip)*128);
            #pragma unroll
            for (int ks = 0; ks < 4; ks++) {
                uint32_t co = ((uint32_t)(ks*32) | khb) ^ swl;
                uint32_t bh[4];
                ldsm4(bh, rowb + co);
                mma16816(sacc[2*ntp],   qh[ks], bh[0], bh[1]);
                mma16816(sacc[2*ntp+1], qh[ks], bh[2], bh[3]);
            }
        }
        #pragma unroll
        for (int nt = 0; nt < 16; nt++) {
            Zr0 += ex2f_(sacc[nt][0]) + ex2f_(sacc[nt][1]);
            Zr1 += ex2f_(sacc[nt][2]) + ex2f_(sacc[nt][3]);
        }
    }
    #pragma unroll
    for (int off = 1; off <= 2; off <<= 1) {
        Zr0 += __shfl_xor_sync(0xffffffffu, Zr0, off);
        Zr1 += __shfl_xor_sync(0xffffffffu, Zr1, off);
    }
    const float lz0 = lg2f_(Zr0);
    const float lz1 = lg2f_(Zr1);

    // ====== PASS B: pipelined — S(c), PV(c-1) from reg P-frags, epi(c) ======
    float oacc[8][4];
    #pragma unroll
    for (int n = 0; n < 8; n++)
        #pragma unroll
        for (int j = 0; j < 4; j++) oacc[n][j] = 0.0f;
    float eacc = 0.0f;
    uint32_t ph[8][4], pl[8][4];

    __syncthreads();
    {
        const size_t tn = (size_t)tile_k0*16384;
        #pragma unroll
        for (int i = 0; i < 4; i++) {
            uint32_t off = (uint32_t)(i*4096 + tid*16);
            cpa16(smb + OKB + off,         (const char*)g_khi  + tn + off);
            cpa16(smb + OKB + 16384 + off, (const char*)g_klo  + tn + off);
            cpa16(smb + OVB + off,         (const char*)g_vthi + tn + off);
            cpa16(smb + OVB + 16384 + off, (const char*)g_vtlo + tn + off);
        }
        CPA_COMMIT();
    }

    for (int c = 0; c < TSEQ/128; c++) {
        __syncthreads();
        if (c < TSEQ/128 - 1) {
            const size_t tn = (size_t)(tile_k0 + c + 1)*16384;
            const uint32_t kdst = smb + OKB + (uint32_t)(((c+1)&1)*32768);
            const uint32_t vdst = smb + OVB + (uint32_t)(((c+1)%3)*32768);
            #pragma unroll
            for (int i = 0; i < 4; i++) {
                uint32_t off = (uint32_t)(i*4096 + tid*16);
                cpa16(kdst + off,         (const char*)g_khi  + tn + off);
                cpa16(kdst + 16384 + off, (const char*)g_klo  + tn + off);
                cpa16(vdst + off,         (const char*)g_vthi + tn + off);
                cpa16(vdst + 16384 + off, (const char*)g_vtlo + tn + off);
            }
            CPA_COMMIT();
            CPA_WAIT1();
        } else {
            CPA_WAIT0();
        }
        __syncthreads();

        const uint32_t kb32 = smb + OKB + (uint32_t)((c&1)*32768);

        // ---- S = Q K^T (3-term) ----
        float sacc[16][4];
        #pragma unroll
        for (int n = 0; n < 16; n++)
            #pragma unroll
            for (int j = 0; j < 4; j++) sacc[n][j] = 0.0f;

        #pragma unroll
        for (int ntp = 0; ntp < 8; ntp++) {
            const uint32_t rowb = kb32 + (uint32_t)((ntp*16 + rip)*128);
            #pragma unroll
            for (int ks = 0; ks < 4; ks++) {
                uint32_t co = ((uint32_t)(ks*32) | khb) ^ swl;
                uint32_t bh[4], bl[4];
                ldsm4(bh, rowb + co);
                ldsm4(bl, rowb + 16384 + co);
                mma16816(sacc[2*ntp],   qh[ks], bh[0], bh[1]);
                mma16816(sacc[2*ntp],   qh[ks], bl[0], bl[1]);
                mma16816(sacc[2*ntp],   ql[ks], bh[0], bh[1]);
                mma16816(sacc[2*ntp+1], qh[ks], bh[2], bh[3]);
                mma16816(sacc[2*ntp+1], qh[ks], bl[2], bl[3]);
                mma16816(sacc[2*ntp+1], ql[ks], bh[2], bh[3]);
            }
        }

        // ---- PV for the PREVIOUS chunk (P-frags from registers) ----
        if (c > 0) {
            const uint32_t vb32 = smb + OVB + (uint32_t)(((c-1)%3)*32768);
            #pragma unroll
            for (int ntp = 0; ntp < 4; ntp++) {
                const uint32_t rowb = vb32 + (uint32_t)((ntp*16 + rip)*256);
                #pragma unroll
                for (int ks = 0; ks < 8; ks++) {
                    uint32_t kb = (uint32_t)(ks*32) | khb;
                    uint32_t co = (kb & 128u) + ((kb & 127u) ^ swl);
                    uint32_t vh[4], vl[4];
                    ldsm4(vh, rowb + co);
                    ldsm4(vl, rowb + 16384 + co);
                    mma16816(oacc[2*ntp],   ph[ks], vh[0], vh[1]);
                    mma16816(oacc[2*ntp],   ph[ks], vl[0], vl[1]);
                    mma16816(oacc[2*ntp],   pl[ks], vh[0], vh[1]);
                    mma16816(oacc[2*ntp+1], ph[ks], vh[2], vh[3]);
                    mma16816(oacc[2*ntp+1], ph[ks], vl[2], vl[3]);
                    mma16816(oacc[2*ntp+1], pl[ks], vh[2], vh[3]);
                }
            }
        }

        // ---- epilogue(c): exp, entropy, attn store, build P-frags ----
        float* arow0 = attn + (rowg + wr + g)*TSEQ + c*128 + 2*tq;
        float* arow1 = arow0 + (size_t)8*TSEQ;
        #pragma unroll
        for (int ks = 0; ks < 8; ks++) {
            #pragma unroll
            for (int h2 = 0; h2 < 2; h2++) {
                int nt = 2*ks + h2;
                float t0 = sacc[nt][0] - lz0, t1 = sacc[nt][1] - lz0;
                float t2 = sacc[nt][2] - lz1, t3 = sacc[nt][3] - lz1;
                float e0 = ex2f_(t0), e1 = ex2f_(t1), e2 = ex2f_(t2), e3 = ex2f_(t3);
                eacc += (e0*t0 + e1*t1) + (e2*t2 + e3*t3);
                stg_cs2(arow0 + nt*8, e0, e1);
                stg_cs2(arow1 + nt*8, e2, e3);
                uint32_t u01 = pk2(e0, e1), u23 = pk2(e2, e3);
                if (h2 == 0) {
                    ph[ks][0] = u01;                 ph[ks][1] = u23;
                    pl[ks][0] = pk2lo(e0, e1, u01);  pl[ks][1] = pk2lo(e2, e3, u23);
                } else {
                    ph[ks][2] = u01;                 ph[ks][3] = u23;
                    pl[ks][2] = pk2lo(e0, e1, u01);  pl[ks][3] = pk2lo(e2, e3, u23);
                }
            }
        }
    }

    // ---- final PV for the last chunk ----
    {
        const int cl = TSEQ/128 - 1;
        const uint32_t vb32 = smb + OVB + (uint32_t)((cl%3)*32768);
        #pragma unroll
        for (int ntp = 0; ntp < 4; ntp++) {
            const uint32_t rowb = vb32 + (uint32_t)((ntp*16 + rip)*256);
            #pragma unroll
            for (int ks = 0; ks < 8; ks++) {
                uint32_t kb = (uint32_t)(ks*32) | khb;
                uint32_t co = (kb & 128u) + ((kb & 127u) ^ swl);
                uint32_t vh[4], vl[4];
                ldsm4(vh, rowb + co);
                ldsm4(vl, rowb + 16384 + co);
                mma16816(oacc[2*ntp],   ph[ks], vh[0], vh[1]);
                mma16816(oacc[2*ntp],   ph[ks], vl[0], vl[1]);
                mma16816(oacc[2*ntp],   pl[ks], vh[0], vh[1]);
                mma16816(oacc[2*ntp+1], ph[ks], vh[2], vh[3]);
                mma16816(oacc[2*ntp+1], ph[ks], vl[2], vl[3]);
                mma16816(oacc[2*ntp+1], pl[ks], vh[2], vh[3]);
            }
        }
    }

    float* orow0 = out + (rowg + wr + g)*HDIM + 2*tq;
    float* orow1 = orow0 + (size_t)8*HDIM;
    #pragma unroll
    for (int nt = 0; nt < 8; nt++) {
        stg_cs2(orow0 + nt*8, oacc[nt][0], oacc[nt][1]);
        stg_cs2(orow1 + nt*8, oacc[nt][2], oacc[nt][3]);
    }

    #pragma unroll
    for (int off = 16; off > 0; off >>= 1)
        eacc += __shfl_xor_sync(0xffffffffu, eacc, off);
    if (lane == 0) s_ent[w] = eacc;
    __syncthreads();
    if (tid == 0) {
        float t = 0.0f;
        #pragma unroll
        for (int i = 0; i < 8; i++) t += s_ent[i];
        atomicAdd(&g_ent, t);
    }
}

// ---------------------------------------------------------------------------
// K3: finalize energy EMA.  H_mean = -ln2 * g_ent / NROWS
// ---------------------------------------------------------------------------
__global__ void fin_kernel(const float* __restrict__ energy, float* __restrict__ eout)
{
    float ent_mean = -0.6931471805599453f * g_ent / (float)NROWS;
    *eout = 0.9f * energy[0] + 0.1f * ent_mean;
}

// ---------------------------------------------------------------------------
extern "C" void kernel_launch(void* const* d_in, const int* in_sizes, int n_in,
                              void* d_out, int out_size)
{
    const float* x      = (const float*)d_in[0];
    const float* Wq     = (const float*)d_in[1];
    const float* Wk     = (const float*)d_in[2];
    const float* Wv     = (const float*)d_in[3];
    const float* energy = (const float*)d_in[4];

    float* out  = (float*)d_out;                               // [B,T,H]
    float* attn = out + (size_t)BATCH*TSEQ*HDIM;               // [B,T,T]
    float* eout = attn + (size_t)BATCH*TSEQ*TSEQ;              // scalar

    cudaFuncSetAttribute(proj_kernel,  cudaFuncAttributeMaxDynamicSharedMemorySize, SMEM_PROJ);
    cudaFuncSetAttribute(attn2_kernel, cudaFuncAttributeMaxDynamicSharedMemorySize, SMEM_ATTN);

    wprep_kernel<<<48, 256>>>(Wq, Wk, Wv);
    proj_kernel<<<NTILE, 512, SMEM_PROJ>>>(x);
    attn2_kernel<<<dim3(TSEQ/128, BATCH), 256, SMEM_ATTN>>>(attn, out);
    fin_kernel<<<1, 1>>>(energy, eout);
}

// round 17
// speedup vs baseline: 1.0493x; 1.0493x over previous
#include <cuda_runtime.h>
#include <cuda_bf16.h>
#include <math.h>
#include <stdint.h>

#define BATCH 4
#define TSEQ  4096
#define DMODEL 1024
#define HDIM  64
#define NROWS (BATCH*TSEQ)
#define NTILE (NROWS/128)

#define SCALE_Q 0.18033688011112042f   // log2(e)/8

// Scratch: preformatted bf16 hi/lo tiles (swizzled smem images)
__device__ __align__(16) __nv_bfloat16 g_qhi[NROWS*HDIM];
__device__ __align__(16) __nv_bfloat16 g_qlo[NROWS*HDIM];
__device__ __align__(16) __nv_bfloat16 g_khi[NROWS*HDIM];
__device__ __align__(16) __nv_bfloat16 g_klo[NROWS*HDIM];
__device__ __align__(16) __nv_bfloat16 g_vthi[NROWS*HDIM];
__device__ __align__(16) __nv_bfloat16 g_vtlo[NROWS*HDIM];
__device__ __align__(16) char g_wimg[16*3*16384];   // [chunk][m][hi 8KB | lo 8KB]
__device__ float g_ent;

__device__ __forceinline__ float ex2f_(float x){ float y; asm("ex2.approx.ftz.f32 %0, %1;" : "=f"(y) : "f"(x)); return y; }
__device__ __forceinline__ float lg2f_(float x){ float y; asm("lg2.approx.f32 %0, %1;" : "=f"(y) : "f"(x)); return y; }

__device__ __forceinline__ uint32_t pk2(float a, float b){
    uint32_t r;
    asm("cvt.rn.bf16x2.f32 %0, %1, %2;" : "=r"(r) : "f"(b), "f"(a));
    return r;
}
__device__ __forceinline__ uint32_t pk2lo(float a, float b, uint32_t u){
    float hi_a = __uint_as_float(u << 16);
    float hi_b = __uint_as_float(u & 0xffff0000u);
    return pk2(a - hi_a, b - hi_b);
}
__device__ __forceinline__ uint32_t smem_u32(const void* p){
    uint32_t a;
    asm("{ .reg .u64 t; cvta.to.shared.u64 t, %1; cvt.u32.u64 %0, t; }" : "=r"(a) : "l"(p));
    return a;
}
__device__ __forceinline__ void cpa16(uint32_t s, const void* g){
    asm volatile("cp.async.cg.shared.global [%0], [%1], 16;" :: "r"(s), "l"(g));
}
#define CPA_COMMIT() asm volatile("cp.async.commit_group;" ::: "memory")
#define CPA_WAIT0()  asm volatile("cp.async.wait_group 0;" ::: "memory")
#define CPA_WAIT1()  asm volatile("cp.async.wait_group 1;" ::: "memory")

// streaming store (evict-first): attn/out are write-once, never re-read
__device__ __forceinline__ void stg_cs2(float* p, float a, float b){
    asm volatile("st.global.cs.v2.f32 [%0], {%1, %2};" :: "l"(p), "f"(a), "f"(b) : "memory");
}

__device__ __forceinline__ void mma16816(float* c, const uint32_t* a, uint32_t b0, uint32_t b1){
    asm volatile("mma.sync.aligned.m16n8k16.row.col.f32.bf16.bf16.f32 "
        "{%0,%1,%2,%3}, {%4,%5,%6,%7}, {%8,%9}, {%0,%1,%2,%3};"
        : "+f"(c[0]), "+f"(c[1]), "+f"(c[2]), "+f"(c[3])
        : "r"(a[0]), "r"(a[1]), "r"(a[2]), "r"(a[3]), "r"(b0), "r"(b1));
}
__device__ __forceinline__ void ldsm4(uint32_t* r, uint32_t addr){
    asm volatile("ldmatrix.sync.aligned.m8n8.x4.shared.b16 {%0,%1,%2,%3}, [%4];"
        : "=r"(r[0]), "=r"(r[1]), "=r"(r[2]), "=r"(r[3]) : "r"(addr));
}

// Q/K/W tiles: 128B rows, row r, byte col cb (0..127)
__device__ __forceinline__ uint32_t swz(int r, int cb){
    return (uint32_t)(r*128 + (cb ^ ((r & 7) << 4)));
}
// VT tiles: 256B rows (128 keys bf16), swizzle within each 128B half
__device__ __forceinline__ uint32_t vswz(int h, int kb){
    return (uint32_t)(h*256 + (kb & 128) + ((kb & 127) ^ ((h & 7) << 4)));
}

// ---------------------------------------------------------------------------
// K0: W preformat. grid 48 (= chunk*3 + m), 256 threads. One 16KB image each.
// ---------------------------------------------------------------------------
__global__ __launch_bounds__(256) void wprep_kernel(
    const float* __restrict__ Wq,
    const float* __restrict__ Wk,
    const float* __restrict__ Wv)
{
    const int m = blockIdx.x % 3;
    const int c = blockIdx.x / 3;
    const float* W = (m == 0) ? Wq : ((m == 1) ? Wk : Wv);
    char* dst = g_wimg + (size_t)blockIdx.x * 16384;
    const int tid = threadIdx.x;
    if (blockIdx.x == 0 && tid == 0) g_ent = 0.0f;
    #pragma unroll
    for (int i = 0; i < 8; i++) {
        int p = i*256 + tid;
        int h = p >> 5, c2 = p & 31;
        float2 v = *(const float2*)&W[(size_t)h*DMODEL + c*64 + 2*c2];
        uint32_t u = pk2(v.x, v.y);
        uint32_t off = swz(h, c2*4);
        *(uint32_t*)(dst + off)        = u;
        *(uint32_t*)(dst + 8192 + off) = pk2lo(v.x, v.y, u);
    }
}

// ---------------------------------------------------------------------------
// K1: fused QKV projection (R13 — passing, near floor).
// ---------------------------------------------------------------------------
#define PJ_XSTG 0              // 2 x 32KB fp32 x staging
#define PJ_XIMG 65536          // xhi 16KB + xlo 16KB
#define PJ_WIMG 98304          // 2 x 48KB preformatted W images
#define SMEM_PROJ 196608
#define PSTG_STRIDE 66

__global__ __launch_bounds__(512, 1) void proj_kernel(const float* __restrict__ x)
{
    extern __shared__ char sm[];
    const int tile = blockIdx.x;
    const int row0 = tile * 128;
    const int tid  = threadIdx.x;
    const int w    = tid >> 5;
    const int lane = tid & 31;
    const int g    = lane >> 2;
    const int tq   = lane & 3;
    const int wm   = w & 7;
    const int wn   = w >> 3;
    const int wr   = 16 * wm;
    const uint32_t smb = smem_u32(sm);

    const int      rip = ((lane >> 4) & 1)*8 + (lane & 7);
    const uint32_t khb = ((lane >> 3) & 1)*16;
    const uint32_t swl = (uint32_t)((lane & 7) << 4);
    const int      ripA = ((lane >> 3) & 1)*8 + (lane & 7);
    const uint32_t khA  = (uint32_t)((lane >> 4) << 4);

    float acc[3][4][4];
    #pragma unroll
    for (int m = 0; m < 3; m++)
        #pragma unroll
        for (int n = 0; n < 4; n++)
            #pragma unroll
            for (int j = 0; j < 4; j++) acc[m][n][j] = 0.0f;

    {
        const char* xg = (const char*)(x + (size_t)row0*DMODEL);
        #pragma unroll
        for (int i = 0; i < 4; i++) {
            int p = i*512 + tid;
            int r = p >> 4, cb = (p & 15)*16;
            cpa16(smb + PJ_XSTG + (uint32_t)(r*256 + cb), xg + (size_t)r*4096 + cb);
        }
        const char* wg = g_wimg;
        #pragma unroll
        for (int i = 0; i < 6; i++) {
            uint32_t off = (uint32_t)(i*8192 + tid*16);
            cpa16(smb + PJ_WIMG + off, wg + off);
        }
        CPA_COMMIT();
    }

    for (int c = 0; c < 16; c++) {
        __syncthreads();
        if (c < 15) {
            const char* xg = (const char*)(x + (size_t)row0*DMODEL + (c+1)*64);
            const uint32_t xdst = smb + PJ_XSTG + (uint32_t)(((c+1)&1)*32768);
            #pragma unroll
            for (int i = 0; i < 4; i++) {
                int p = i*512 + tid;
                int r = p >> 4, cb = (p & 15)*16;
                cpa16(xdst + (uint32_t)(r*256 + cb), xg + (size_t)r*4096 + cb);
            }
            const char* wg = g_wimg + (size_t)(c+1)*49152;
            const uint32_t wdst = smb + PJ_WIMG + (uint32_t)(((c+1)&1)*49152);
            #pragma unroll
            for (int i = 0; i < 6; i++) {
                uint32_t off = (uint32_t)(i*8192 + tid*16);
                cpa16(wdst + off, wg + off);
            }
            CPA_COMMIT();
            CPA_WAIT1();
        } else {
            CPA_WAIT0();
        }
        __syncthreads();

        {
            const float* stg = (const float*)(sm + PJ_XSTG + (c&1)*32768);
            #pragma unroll
            for (int i = 0; i < 8; i++) {
                int p = i*512 + tid;
                int r = p >> 5, c2 = p & 31;
                float2 v = *(const float2*)&stg[r*64 + 2*c2];
                uint32_t u = pk2(v.x, v.y);
                uint32_t off = swz(r, c2*4);
                *(uint32_t*)(sm + PJ_XIMG + off)         = u;
                *(uint32_t*)(sm + PJ_XIMG + 16384 + off) = pk2lo(v.x, v.y, u);
            }
        }
        __syncthreads();

        const uint32_t xrowA = smb + PJ_XIMG + (uint32_t)((wr + ripA)*128);
        const uint32_t wbuf  = smb + PJ_WIMG + (uint32_t)((c&1)*49152);
        #pragma unroll
        for (int ks = 0; ks < 4; ks++) {
            uint32_t coA = ((uint32_t)(ks*32) | khA) ^ swl;
            uint32_t ah[4], al[4];
            ldsm4(ah, xrowA + coA);
            ldsm4(al, xrowA + 16384 + coA);
            uint32_t co = ((uint32_t)(ks*32) | khb) ^ swl;
            #pragma unroll
            for (int m = 0; m < 3; m++) {
                #pragma unroll
                for (int ntp = 0; ntp < 2; ntp++) {
                    uint32_t rowb = wbuf + (uint32_t)(m*16384 + (wn*32 + ntp*16 + rip)*128);
                    uint32_t bh[4], bl[4];
                    ldsm4(bh, rowb + co);
                    ldsm4(bl, rowb + 8192 + co);
                    mma16816(acc[m][2*ntp],   ah, bh[0], bh[1]);
                    mma16816(acc[m][2*ntp+1], ah, bh[2], bh[3]);
                    mma16816(acc[m][2*ntp],   ah, bl[0], bl[1]);
                    mma16816(acc[m][2*ntp+1], ah, bl[2], bl[3]);
                    mma16816(acc[m][2*ntp],   al, bh[0], bh[1]);
                    mma16816(acc[m][2*ntp+1], al, bh[2], bh[3]);
                }
            }
        }
    }

    #pragma unroll
    for (int m = 0; m < 2; m++) {
        const float sc = (m == 0) ? SCALE_Q : 1.0f;
        char* dhi = (char*)((m == 0) ? g_qhi : g_khi) + (size_t)tile*16384;
        char* dlo = (char*)((m == 0) ? g_qlo : g_klo) + (size_t)tile*16384;
        #pragma unroll
        for (int nt = 0; nt < 4; nt++) {
            float c0 = acc[m][nt][0]*sc, c1 = acc[m][nt][1]*sc;
            float c2 = acc[m][nt][2]*sc, c3 = acc[m][nt][3]*sc;
            int cb = wn*64 + nt*16 + tq*4;
            uint32_t u0 = pk2(c0, c1), u1 = pk2(c2, c3);
            *(uint32_t*)(dhi + swz(wr+g,   cb)) = u0;
            *(uint32_t*)(dhi + swz(wr+g+8, cb)) = u1;
            *(uint32_t*)(dlo + swz(wr+g,   cb)) = pk2lo(c0, c1, u0);
            *(uint32_t*)(dlo + swz(wr+g+8, cb)) = pk2lo(c2, c3, u1);
        }
    }

    __syncthreads();
    float* stg = (float*)sm;
    #pragma unroll
    for (int nt = 0; nt < 4; nt++) {
        int hc = wn*32 + nt*8 + tq*2;
        *(float2*)&stg[(wr+g)*PSTG_STRIDE + hc]   = make_float2(acc[2][nt][0], acc[2][nt][1]);
        *(float2*)&stg[(wr+g+8)*PSTG_STRIDE + hc] = make_float2(acc[2][nt][2], acc[2][nt][3]);
    }
    __syncthreads();
    {
        char* dhi = (char*)g_vthi + (size_t)tile*16384;
        char* dlo = (char*)g_vtlo + (size_t)tile*16384;
        int h = tid & 63, kp0 = tid >> 6;
        #pragma unroll
        for (int i = 0; i < 8; i++) {
            int pi = kp0 + 8*i;
            int k = 2*pi;
            float v0 = stg[k*PSTG_STRIDE + h];
            float v1 = stg[(k+1)*PSTG_STRIDE + h];
            uint32_t off = vswz(h, 4*pi);
            uint32_t u = pk2(v0, v1);
            *(uint32_t*)(dhi + off) = u;
            *(uint32_t*)(dlo + off) = pk2lo(v0, v1, u);
        }
    }
}

// ---------------------------------------------------------------------------
// K2: fused attention, two-pass, 256 threads (R15 base).
// Changes vs R15: pass A uses 256-key chunks (halved barrier count);
// S and PV MMA chains interleaved across the two accumulators.
// ---------------------------------------------------------------------------
#define OQHI 0
#define OQLO 16384
#define OBUF 32768
#define SMEM_ATTN 163840

__global__ __launch_bounds__(256, 1) void attn2_kernel(float* __restrict__ attn,
                                                       float* __restrict__ out)
{
    extern __shared__ char sm[];
    __shared__ float s_ent[8];

    const int tid  = threadIdx.x;
    const int w    = tid >> 5;
    const int lane = tid & 31;
    const int g    = lane >> 2;
    const int tq   = lane & 3;
    const int b    = blockIdx.y;
    const int q0   = blockIdx.x * 128;
    const size_t rowg = (size_t)b*TSEQ + q0;
    const int wr  = 16 * w;
    const uint32_t smb = smem_u32(sm);

    const int      rip = ((lane >> 4) & 1)*8 + (lane & 7);
    const uint32_t khb = ((lane >> 3) & 1)*16;
    const uint32_t swl = (uint32_t)((lane & 7) << 4);

    const int tile_q  = b*(TSEQ/128) + blockIdx.x;
    const int tile_k0 = b*(TSEQ/128);

    // Q tile + pass-A chunk 0 (khi for 256 keys = 2 tiles = 32KB)
    {
        const char* gq_hi = (const char*)g_qhi + (size_t)tile_q*16384;
        const char* gq_lo = (const char*)g_qlo + (size_t)tile_q*16384;
        #pragma unroll
        for (int i = 0; i < 4; i++) {
            uint32_t off = (uint32_t)(i*4096 + tid*16);
            cpa16(smb + OQHI + off, gq_hi + off);
            cpa16(smb + OQLO + off, gq_lo + off);
        }
        const char* gk_hi = (const char*)g_khi + (size_t)tile_k0*16384;
        #pragma unroll
        for (int i = 0; i < 8; i++) {
            uint32_t off = (uint32_t)(i*4096 + tid*16);
            cpa16(smb + OBUF + off, gk_hi + off);
        }
        CPA_COMMIT();
        CPA_WAIT0();
    }
    __syncthreads();

    uint32_t qh[4][4], ql[4][4];
    #pragma unroll
    for (int ks = 0; ks < 4; ks++) {
        int kb = ks*32 + tq*4;
        qh[ks][0] = *(const uint32_t*)(sm + OQHI + swz(wr+g,   kb));
        qh[ks][1] = *(const uint32_t*)(sm + OQHI + swz(wr+g+8, kb));
        qh[ks][2] = *(const uint32_t*)(sm + OQHI + swz(wr+g,   kb+16));
        qh[ks][3] = *(const uint32_t*)(sm + OQHI + swz(wr+g+8, kb+16));
        ql[ks][0] = *(const uint32_t*)(sm + OQLO + swz(wr+g,   kb));
        ql[ks][1] = *(const uint32_t*)(sm + OQLO + swz(wr+g+8, kb));
        ql[ks][2] = *(const uint32_t*)(sm + OQLO + swz(wr+g,   kb+16));
        ql[ks][3] = *(const uint32_t*)(sm + OQLO + swz(wr+g+8, kb+16));
    }

    // ============ PASS A: rowsums Z (1-term), 256-key chunks ============
    float Zr0 = 0.f, Zr1 = 0.f;
    for (int c = 0; c < TSEQ/256; c++) {
        __syncthreads();
        if (c < TSEQ/256 - 1) {
            const char* gk_hi = (const char*)g_khi + (size_t)(tile_k0 + (c+1)*2)*16384;
            const uint32_t dst = smb + OBUF + (uint32_t)(((c+1)&1)*32768);
            #pragma unroll
            for (int i = 0; i < 8; i++) {
                uint32_t off = (uint32_t)(i*4096 + tid*16);
                cpa16(dst + off, gk_hi + off);
            }
            CPA_COMMIT();
            CPA_WAIT1();
        } else {
            CPA_WAIT0();
        }
        __syncthreads();

        const uint32_t buf = smb + OBUF + (uint32_t)((c&1)*32768);
        #pragma unroll
        for (int kh = 0; kh < 2; kh++) {
            const uint32_t kb32 = buf + (uint32_t)(kh*16384);
            float sacc[16][4];
            #pragma unroll
            for (int n = 0; n < 16; n++)
                #pragma unroll
                for (int j = 0; j < 4; j++) sacc[n][j] = 0.0f;
            #pragma unroll
            for (int ntp = 0; ntp < 8; ntp++) {
                const uint32_t rowb = kb32 + (uint32_t)((ntp*16 + rip)*128);
                #pragma unroll
                for (int ks = 0; ks < 4; ks++) {
                    uint32_t co = ((uint32_t)(ks*32) | khb) ^ swl;
                    uint32_t bh[4];
                    ldsm4(bh, rowb + co);
                    mma16816(sacc[2*ntp],   qh[ks], bh[0], bh[1]);
                    mma16816(sacc[2*ntp+1], qh[ks], bh[2], bh[3]);
                }
            }
            #pragma unroll
            for (int nt = 0; nt < 16; nt++) {
                Zr0 += ex2f_(sacc[nt][0]) + ex2f_(sacc[nt][1]);
                Zr1 += ex2f_(sacc[nt][2]) + ex2f_(sacc[nt][3]);
            }
        }
    }
    #pragma unroll
    for (int off = 1; off <= 2; off <<= 1) {
        Zr0 += __shfl_xor_sync(0xffffffffu, Zr0, off);
        Zr1 += __shfl_xor_sync(0xffffffffu, Zr1, off);
    }
    const float lz0 = lg2f_(Zr0);
    const float lz1 = lg2f_(Zr1);

    // ================== PASS B: normalized P write + O = P V =================
    float oacc[8][4];
    #pragma unroll
    for (int n = 0; n < 8; n++)
        #pragma unroll
        for (int j = 0; j < 4; j++) oacc[n][j] = 0.0f;
    float eacc = 0.0f;

    __syncthreads();
    {
        const size_t tn = (size_t)tile_k0*16384;
        #pragma unroll
        for (int i = 0; i < 4; i++) {
            uint32_t off = (uint32_t)(i*4096 + tid*16);
            cpa16(smb + OBUF + off,         (const char*)g_khi  + tn + off);
            cpa16(smb + OBUF + 16384 + off, (const char*)g_klo  + tn + off);
            cpa16(smb + OBUF + 32768 + off, (const char*)g_vthi + tn + off);
            cpa16(smb + OBUF + 49152 + off, (const char*)g_vtlo + tn + off);
        }
        CPA_COMMIT();
    }

    for (int c = 0; c < TSEQ/128; c++) {
        __syncthreads();
        if (c < TSEQ/128 - 1) {
            const size_t tn = (size_t)(tile_k0 + c + 1)*16384;
            const uint32_t dst = smb + OBUF + (uint32_t)(((c+1)&1)*65536);
            #pragma unroll
            for (int i = 0; i < 4; i++) {
                uint32_t off = (uint32_t)(i*4096 + tid*16);
                cpa16(dst + off,         (const char*)g_khi  + tn + off);
                cpa16(dst + 16384 + off, (const char*)g_klo  + tn + off);
                cpa16(dst + 32768 + off, (const char*)g_vthi + tn + off);
                cpa16(dst + 49152 + off, (const char*)g_vtlo + tn + off);
            }
            CPA_COMMIT();
            CPA_WAIT1();
        } else {
            CPA_WAIT0();
        }
        __syncthreads();

        const uint32_t kb32 = smb + OBUF + (uint32_t)((c&1)*65536);
        const uint32_t vb32 = kb32 + 32768;

        float sacc[16][4];
        #pragma unroll
        for (int n = 0; n < 16; n++)
            #pragma unroll
            for (int j = 0; j < 4; j++) sacc[n][j] = 0.0f;

        // S = Q K^T (3-term), interleaved across the two accumulators
        #pragma unroll
        for (int ntp = 0; ntp < 8; ntp++) {
            const uint32_t rowb = kb32 + (uint32_t)((ntp*16 + rip)*128);
            #pragma unroll
            for (int ks = 0; ks < 4; ks++) {
                uint32_t co = ((uint32_t)(ks*32) | khb) ^ swl;
                uint32_t bh[4], bl[4];
                ldsm4(bh, rowb + co);
                ldsm4(bl, rowb + 16384 + co);
                mma16816(sacc[2*ntp],   qh[ks], bh[0], bh[1]);
                mma16816(sacc[2*ntp+1], qh[ks], bh[2], bh[3]);
                mma16816(sacc[2*ntp],   qh[ks], bl[0], bl[1]);
                mma16816(sacc[2*ntp+1], qh[ks], bl[2], bl[3]);
                mma16816(sacc[2*ntp],   ql[ks], bh[0], bh[1]);
                mma16816(sacc[2*ntp+1], ql[ks], bh[2], bh[3]);
            }
        }

        uint32_t ph[8][4], pl[8][4];
        float* arow0 = attn + (rowg + wr + g)*TSEQ + c*128 + 2*tq;
        float* arow1 = arow0 + (size_t)8*TSEQ;
        #pragma unroll
        for (int ks = 0; ks < 8; ks++) {
            #pragma unroll
            for (int h2 = 0; h2 < 2; h2++) {
                int nt = 2*ks + h2;
                float t0 = sacc[nt][0] - lz0, t1 = sacc[nt][1] - lz0;
                float t2 = sacc[nt][2] - lz1, t3 = sacc[nt][3] - lz1;
                float e0 = ex2f_(t0), e1 = ex2f_(t1), e2 = ex2f_(t2), e3 = ex2f_(t3);
                eacc += (e0*t0 + e1*t1) + (e2*t2 + e3*t3);
                stg_cs2(arow0 + nt*8, e0, e1);
                stg_cs2(arow1 + nt*8, e2, e3);
                uint32_t u01 = pk2(e0, e1), u23 = pk2(e2, e3);
                if (h2 == 0) {
                    ph[ks][0] = u01;                 ph[ks][1] = u23;
                    pl[ks][0] = pk2lo(e0, e1, u01);  pl[ks][1] = pk2lo(e2, e3, u23);
                } else {
                    ph[ks][2] = u01;                 ph[ks][3] = u23;
                    pl[ks][2] = pk2lo(e0, e1, u01);  pl[ks][3] = pk2lo(e2, e3, u23);
                }
            }
        }

        // O += P V, interleaved across the two accumulators
        #pragma unroll
        for (int ntp = 0; ntp < 4; ntp++) {
            const uint32_t rowb = vb32 + (uint32_t)((ntp*16 + rip)*256);
            #pragma unroll
            for (int ks = 0; ks < 8; ks++) {
                uint32_t kb = (uint32_t)(ks*32) | khb;
                uint32_t co = (kb & 128u) + ((kb & 127u) ^ swl);
                uint32_t vh[4], vl[4];
                ldsm4(vh, rowb + co);
                ldsm4(vl, rowb + 16384 + co);
                mma16816(oacc[2*ntp],   ph[ks], vh[0], vh[1]);
                mma16816(oacc[2*ntp+1], ph[ks], vh[2], vh[3]);
                mma16816(oacc[2*ntp],   ph[ks], vl[0], vl[1]);
                mma16816(oacc[2*ntp+1], ph[ks], vl[2], vl[3]);
                mma16816(oacc[2*ntp],   pl[ks], vh[0], vh[1]);
                mma16816(oacc[2*ntp+1], pl[ks], vh[2], vh[3]);
            }
        }
    }

    float* orow0 = out + (rowg + wr + g)*HDIM + 2*tq;
    float* orow1 = orow0 + (size_t)8*HDIM;
    #pragma unroll
    for (int nt = 0; nt < 8; nt++) {
        stg_cs2(orow0 + nt*8, oacc[nt][0], oacc[nt][1]);
        stg_cs2(orow1 + nt*8, oacc[nt][2], oacc[nt][3]);
    }

    #pragma unroll
    for (int off = 16; off > 0; off >>= 1)
        eacc += __shfl_xor_sync(0xffffffffu, eacc, off);
    if (lane == 0) s_ent[w] = eacc;
    __syncthreads();
    if (tid == 0) {
        float t = 0.0f;
        #pragma unroll
        for (int i = 0; i < 8; i++) t += s_ent[i];
        atomicAdd(&g_ent, t);
    }
}

// ---------------------------------------------------------------------------
// K3: finalize energy EMA.  H_mean = -ln2 * g_ent / NROWS
// ---------------------------------------------------------------------------
__global__ void fin_kernel(const float* __restrict__ energy, float* __restrict__ eout)
{
    float ent_mean = -0.6931471805599453f * g_ent / (float)NROWS;
    *eout = 0.9f * energy[0] + 0.1f * ent_mean;
}

// ---------------------------------------------------------------------------
extern "C" void kernel_launch(void* const* d_in, const int* in_sizes, int n_in,
                              void* d_out, int out_size)
{
    const float* x      = (const float*)d_in[0];
    const float* Wq     = (const float*)d_in[1];
    const float* Wk     = (const float*)d_in[2];
    const float* Wv     = (const float*)d_in[3];
    const float* energy = (const float*)d_in[4];

    float* out  = (float*)d_out;                               // [B,T,H]
    float* attn = out + (size_t)BATCH*TSEQ*HDIM;               // [B,T,T]
    float* eout = attn + (size_t)BATCH*TSEQ*TSEQ;              // scalar

    cudaFuncSetAttribute(proj_kernel,  cudaFuncAttributeMaxDynamicSharedMemorySize, SMEM_PROJ);
    cudaFuncSetAttribute(attn2_kernel, cudaFuncAttributeMaxDynamicSharedMemorySize, SMEM_ATTN);

    wprep_kernel<<<48, 256>>>(Wq, Wk, Wv);
    proj_kernel<<<NTILE, 512, SMEM_PROJ>>>(x);
    attn2_kernel<<<dim3(TSEQ/128, BATCH), 256, SMEM_ATTN>>>(attn, out);
    fin_kernel<<<1, 1>>>(energy, eout);
}